// round 1
// baseline (speedup 1.0000x reference)
#include <cuda_runtime.h>
#include <math.h>

#define NPTS   8192
#define BATCH  2
#define NQ_TOT (2 * BATCH * NPTS)   // 32768 queries total (both passes)

#define THREADS 128
#define IPT     4                   // queries per thread
#define QPB     (THREADS * IPT)     // 512 queries per block
#define QCHUNKS ((2 * BATCH * NPTS) / QPB)  // 64
#define CHUNKS_PER_PB (NPTS / QPB)  // 16 chunks per (pass,b)
#define JSPLIT  8
#define JLEN    (NPTS / JSPLIT)     // 1024

// Scratch (no allocations allowed in kernel_launch)
// g_db[pass][b][n]: pass 0 = database built from pred (queries are gt),
//                   pass 1 = database built from gt   (queries are pred).
// Stored as (-2x, -2y, -2z, |p|^2) so inner loop is 3 FFMA.
__device__ float4 g_db[2][BATCH][NPTS];
__device__ unsigned int g_minbits[NQ_TOT];

// Order-preserving float <-> uint mapping (for atomicMin on possibly-negative t)
__device__ __forceinline__ unsigned int enc_f(float f) {
    unsigned int u = __float_as_uint(f);
    return (u & 0x80000000u) ? ~u : (u | 0x80000000u);
}
__device__ __forceinline__ float dec_f(unsigned int u) {
    u = (u & 0x80000000u) ? (u ^ 0x80000000u) : ~u;
    return __uint_as_float(u);
}

__global__ void prep_kernel(const float* __restrict__ pred,
                            const float* __restrict__ gt) {
    int tid = blockIdx.x * blockDim.x + threadIdx.x;
    if (tid < NQ_TOT) g_minbits[tid] = 0xFFFFFFFFu;  // encoded +max
    if (tid < BATCH * NPTS) {
        int b = tid / NPTS, n = tid % NPTS;
        float px = pred[3 * tid + 0], py = pred[3 * tid + 1], pz = pred[3 * tid + 2];
        g_db[0][b][n] = make_float4(-2.0f * px, -2.0f * py, -2.0f * pz,
                                    px * px + py * py + pz * pz);
        float gx = gt[3 * tid + 0], gy = gt[3 * tid + 1], gz = gt[3 * tid + 2];
        g_db[1][b][n] = make_float4(-2.0f * gx, -2.0f * gy, -2.0f * gz,
                                    gx * gx + gy * gy + gz * gz);
    }
}

// Grid: (QCHUNKS, JSPLIT). Each block: 512 queries x 1024 database points.
__global__ void __launch_bounds__(THREADS)
min_kernel(const float* __restrict__ pred, const float* __restrict__ gt) {
    __shared__ float4 tile[JLEN];   // 16 KB

    int qblk = blockIdx.x;                 // 0..63
    int pb   = qblk / CHUNKS_PER_PB;       // pass*BATCH + b, uniform per block
    int pass = pb >> 1;
    int b    = pb & 1;
    int nbase = (qblk % CHUNKS_PER_PB) * QPB;

    const float*  qsrc = (pass == 0) ? gt : pred;   // queries
    const float4* db   = &g_db[pass][b][0];
    int jbase = blockIdx.y * JLEN;

    // cooperative tile load (broadcast-reused by all threads)
    for (int t = threadIdx.x; t < JLEN; t += THREADS)
        tile[t] = db[jbase + t];
    __syncthreads();

    float qx[IPT], qy[IPT], qz[IPT], m[IPT];
#pragma unroll
    for (int k = 0; k < IPT; k++) {
        int n = nbase + k * THREADS + threadIdx.x;
        const float* q = qsrc + ((long)b * NPTS + n) * 3;
        qx[k] = q[0]; qy[k] = q[1]; qz[k] = q[2];
        m[k] = 3.4e38f;
    }

#pragma unroll 4
    for (int j = 0; j < JLEN; j++) {
        float4 p = tile[j];
#pragma unroll
        for (int k = 0; k < IPT; k++) {
            // t = |p|^2 - 2<q,p>   (3 FFMA, db pre-scaled by -2)
            float t = __fmaf_rn(qx[k], p.x,
                      __fmaf_rn(qy[k], p.y,
                      __fmaf_rn(qz[k], p.z, p.w)));
            m[k] = fminf(m[k], t);
        }
    }

#pragma unroll
    for (int k = 0; k < IPT; k++) {
        int q = pass * (BATCH * NPTS) + b * NPTS + nbase + k * THREADS + threadIdx.x;
        atomicMin(&g_minbits[q], enc_f(m[k]));   // order-independent -> deterministic
    }
}

__global__ void __launch_bounds__(1024)
reduce_kernel(const float* __restrict__ pred, const float* __restrict__ gt,
              float* __restrict__ out) {
    __shared__ float sbuf[1024];
    int tid = threadIdx.x;
    float s = 0.0f;
    for (int q = tid; q < NQ_TOT; q += 1024) {
        int pass = q / (BATCH * NPTS);
        int r    = q % (BATCH * NPTS);          // b*NPTS + n
        const float* qsrc = (pass == 0) ? gt : pred;
        float x = qsrc[3 * r + 0], y = qsrc[3 * r + 1], z = qsrc[3 * r + 2];
        float g2 = x * x + y * y + z * z;
        float t  = dec_f(g_minbits[q]);
        s += sqrtf(fmaxf(g2 + t, 0.0f));
    }
    sbuf[tid] = s;
    __syncthreads();
    for (int off = 512; off > 0; off >>= 1) {
        if (tid < off) sbuf[tid] += sbuf[tid + off];
        __syncthreads();
    }
    if (tid == 0) out[0] = sbuf[0] / (float)(BATCH * NPTS);
}

extern "C" void kernel_launch(void* const* d_in, const int* in_sizes, int n_in,
                              void* d_out, int out_size) {
    const float* pred = (const float*)d_in[0];
    const float* gt   = (const float*)d_in[1];
    float* out = (float*)d_out;

    prep_kernel<<<(NQ_TOT + 255) / 256, 256>>>(pred, gt);
    dim3 grid(QCHUNKS, JSPLIT);
    min_kernel<<<grid, THREADS>>>(pred, gt);
    reduce_kernel<<<1, 1024>>>(pred, gt, out);
}